// round 1
// baseline (speedup 1.0000x reference)
#include <cuda_runtime.h>
#include <math.h>

#define Nn 64
#define Cc 256
#define Tt 64
#define Vv 25
#define Kk 8
#define VNh 5
#define VT 30
#define CG 32
#define HH 8
#define OO 256
#define OG 32
#define TOPK 9

// ---------------- device scratch (no allocations allowed) ----------------
__device__ float g_pooled[Nn * Cc * VT];         // ~2 MB
__device__ float g_adjn[Kk * VT * VT];           // normalized base adjacency
__device__ float g_adj[Nn * Kk * VT * VT];       // per-sample adj_full, ~7.4 MB

// ---------------- kernel 0: normalized adjacency ----------------
__global__ void k_adjn(const float* __restrict__ adjc, const float* __restrict__ ei) {
    int r = threadIdx.x;
    if (r < Kk * VT) {
        int base = r * VT;
        float row[VT];
        float s = 0.f;
#pragma unroll
        for (int w = 0; w < VT; w++) {
            float v = ei[base + w] * adjc[base + w];
            row[w] = v;
            s += fabsf(v);
        }
        float inv = 1.f / (s + 1e-8f);
#pragma unroll
        for (int w = 0; w < VT; w++) g_adjn[base + w] = row[w] * inv;
    }
}

// ---------------- kernel 1: pooled = mean_t(xv) ----------------
__global__ void k_pool(const float* __restrict__ x, const float* __restrict__ hj) {
    int tid = blockIdx.x * blockDim.x + threadIdx.x;
    if (tid >= Nn * Cc * VT) return;
    int v = tid % VT;
    int c = (tid / VT) % Cc;
    int n = tid / (VT * Cc);
    float val;
    if (v < Vv) {
        const float* p = x + ((n * Cc + c) * Tt) * Vv + v;
        float s = 0.f;
#pragma unroll 8
        for (int t = 0; t < Tt; t++) s += p[t * Vv];
        val = s * (1.f / (float)Tt);
    } else {
        val = hj[(v - Vv) * Cc + c];
    }
    g_pooled[(n * Cc + c) * VT + v] = val;
}

// ---------------- kernel 2: per-sample hypergraph adjacency ----------------
__global__ __launch_bounds__(256) void k_hyper(
    const float* __restrict__ tvw, const float* __restrict__ tvb,
    const float* __restrict__ t1w, const float* __restrict__ t1b,
    const float* __restrict__ t2w, const float* __restrict__ t2b,
    const float* __restrict__ alpha) {
    // static smem: 12240 floats = 48960 B (< 48KB limit)
    __shared__ float buf[Cc * VT];      // phase0: pooled slice; later: incidence (7200 used)
    __shared__ float vproj[Kk * VT * HH];  // [k][v][h] 1920
    __shared__ float w1s[Kk * HH * VT];    // [q=k*8+h][v] 1920
    __shared__ float wt[Kk * VT];          // weights 240
    __shared__ float dv[Kk * VT];          // d values 240
    __shared__ float rs[Kk * VT];          // row sums (inc_w) 240

    int n = blockIdx.x;
    int tid = threadIdx.x;

    // phase 0: load pooled for this n
    for (int e = tid; e < Cc * VT; e += 256) buf[e] = g_pooled[n * Cc * VT + e];
    __syncthreads();

    // phase 1: vproj[k][v][h], w1s[q][v]
    for (int e = tid; e < 2 * Kk * VT * HH; e += 256) {
        if (e < Kk * VT * HH) {
            int k = e / (VT * HH);
            int v = (e / HH) % VT;
            int h = e % HH;
            float acc = tvb[k * HH + h];
            const float* w = tvw + (k * HH + h) * CG;
            const float* p = buf + (k * CG) * VT + v;
#pragma unroll 8
            for (int c = 0; c < CG; c++) acc += p[c * VT] * w[c];
            vproj[k * (VT * HH) + v * HH + h] = acc;
        } else {
            int e2 = e - Kk * VT * HH;
            int q = e2 / VT;       // q = k*8+h
            int v = e2 % VT;
            int k = q / HH;
            float acc = t1b[q];
            const float* w = t1w + q * CG;
            const float* p = buf + (k * CG) * VT + v;
#pragma unroll 8
            for (int c = 0; c < CG; c++) acc += p[c * VT] * w[c];
            w1s[q * VT + v] = (acc >= 0.f) ? acc : 0.01f * acc;  // leaky_relu
        }
    }
    __syncthreads();

    // phase 2: weights = tanh(w2 @ w1) ; zero incidence (reuse buf)
    float* incid = buf;
    for (int e = tid; e < Kk * VT * VT; e += 256) incid[e] = 0.f;
    if (tid < Kk * VT) {
        int k = tid / VT, v = tid % VT;
        float acc = t2b[k];
        const float* w = t2w + k * (Kk * HH);
#pragma unroll 8
        for (int q = 0; q < Kk * HH; q++) acc += w1s[q * VT + v] * w[q];
        wt[tid] = tanhf(acc);
    }
    __syncthreads();

    // phase 3: per row (k,u): distances, top-9, softmax -> incidence
    if (tid < Kk * VT) {
        int k = tid / VT, u = tid % VT;
        float vu[HH];
#pragma unroll
        for (int h = 0; h < HH; h++) vu[h] = vproj[k * (VT * HH) + u * HH + h];
        float nd[VT];
#pragma unroll
        for (int w = 0; w < VT; w++) {
            float d2 = 0.f;
#pragma unroll
            for (int h = 0; h < HH; h++) {
                float df = vu[h] - vproj[k * (VT * HH) + w * HH + h];
                d2 += df * df;
            }
            nd[w] = (d2 > 0.f) ? -sqrtf(d2) : 0.f;  // -dist
        }
        float vals[TOPK];
        int ids[TOPK];
        unsigned used = 0u;
#pragma unroll
        for (int j = 0; j < TOPK; j++) {
            float best = -INFINITY;
            int bi = 0;
#pragma unroll
            for (int w = 0; w < VT; w++) {
                bool free_w = ((used >> w) & 1u) == 0u;
                if (free_w && nd[w] > best) { best = nd[w]; bi = w; }
            }
            vals[j] = best;
            ids[j] = bi;
            used |= (1u << bi);
        }
        float m = vals[0];
        float pr[TOPK];
        float se = 0.f;
#pragma unroll
        for (int j = 0; j < TOPK; j++) { pr[j] = expf(vals[j] - m); se += pr[j]; }
        float inv = 1.f / se;
#pragma unroll
        for (int j = 0; j < TOPK; j++) incid[k * (VT * VT) + u * VT + ids[j]] = pr[j] * inv;
    }
    __syncthreads();

    // phase 4: column sums -> dv, row sums of inc_w -> rs
    if (tid < 2 * Kk * VT) {
        if (tid < Kk * VT) {
            int k = tid / VT, v = tid % VT;
            float s = 0.f;
#pragma unroll 6
            for (int u = 0; u < VT; u++) s += fabsf(incid[k * (VT * VT) + u * VT + v]);
            dv[tid] = wt[tid] / (s + 1e-8f);
        } else {
            int e = tid - Kk * VT;
            int k = e / VT, u = e % VT;
            float s = 0.f;
#pragma unroll 6
            for (int v = 0; v < VT; v++)
                s += fabsf(incid[k * (VT * VT) + u * VT + v] * wt[k * VT + v]);
            rs[e] = s + 1e-8f;
        }
    }
    __syncthreads();

    // phase 5: adj_full = adjn + relu(alpha) * hyper_adj
    float ra = fmaxf(alpha[0], 0.f);
    for (int e = tid; e < Kk * VT * VT; e += 256) {
        int k = e / (VT * VT);
        int u = (e / VT) % VT;
        int w = e % VT;
        const float* ru = incid + k * (VT * VT) + u * VT;
        const float* rw = incid + k * (VT * VT) + w * VT;
        const float* dk = dv + k * VT;
        const float* wk = wt + k * VT;
        float ha = 0.f;
#pragma unroll 6
        for (int v = 0; v < VT; v++) ha += ru[v] * wk[v] * dk[v] * rw[v];
        ha /= rs[k * VT + u];
        g_adj[n * (Kk * VT * VT) + e] = g_adjn[e] + ra * ha;
    }
}

// ---------------- kernel 3: fused dense conv + graph aggregate + BN + relu ----------------
// grid: Nn*Kk*(Tt/8) blocks. smem layout (floats):
//   As    [0,800)       : adj_full rows u<25, padded to 32 cols
//   rowsA [800,828)     : row sums of A (u padded to 28)
//   Ws    [828,1884)    : conv weight [o*33+c]
//   Xs    [1884,11100)  : X tile [row=c*8+tt][36]
//   Bs    [11100,18268) : B tile [row][28]
#define SM_AS 0
#define SM_RA 800
#define SM_WS 828
#define SM_XS 1884
#define SM_BS 11100
#define SM_TOTAL_FLOATS 18268

__global__ __launch_bounds__(256) void k_main(
    const float* __restrict__ x, const float* __restrict__ hj,
    const float* __restrict__ cdw, const float* __restrict__ cdb,
    const float* __restrict__ gam, const float* __restrict__ bet,
    float* __restrict__ out) {
    extern __shared__ float sm[];
    float* As = sm + SM_AS;
    float* rowsA = sm + SM_RA;
    float* Ws = sm + SM_WS;
    float* Xs = sm + SM_XS;
    float* Bs = sm + SM_BS;

    int bid = blockIdx.x;
    int tb = bid & 7;
    int k = (bid >> 3) & 7;
    int n = bid >> 6;
    int tid = threadIdx.x;

    // load A (25 rows x 30, padded to 32)
    const float* gA = g_adj + (n * Kk + k) * (VT * VT);
    for (int e = tid; e < 25 * 32; e += 256) {
        int v = e & 31;
        As[e] = (v < VT) ? gA[(e >> 5) * VT + v] : 0.f;
    }
    // load conv weight, padded stride 33
    for (int e = tid; e < 32 * 32; e += 256) {
        int o = e >> 5, c = e & 31;
        Ws[o * 33 + c] = cdw[(k * OG + o) * CG + c];
    }
    // load X tile (c in [0,32), tt in [0,8), v in [0,25)): contiguous 200 floats per c
    {
        const float* gx = x + ((n * Cc + k * CG) * Tt + tb * 8) * Vv;
        for (int e = tid; e < 32 * 8 * 25; e += 256) {
            int c = e / 200;
            int r = e - c * 200;
            int ttl = r / 25;
            int v = r - ttl * 25;
            Xs[(c * 8 + ttl) * 36 + v] = gx[c * (Tt * Vv) + r];
        }
        for (int e = tid; e < 32 * 8 * 5; e += 256) {
            int c = e / 40;
            int r = e - c * 40;
            int ttl = r / 5;
            int j = r - ttl * 5;
            Xs[(c * 8 + ttl) * 36 + 25 + j] = hj[j * Cc + k * CG + c];
        }
        for (int e = tid; e < 32 * 8 * 2; e += 256) {
            int row = e >> 1;
            Xs[row * 36 + 30 + (e & 1)] = 0.f;
        }
    }
    __syncthreads();

    // row sums of A (for conv bias term)
    if (tid < 28) {
        float s = 0.f;
        if (tid < 25) {
#pragma unroll
            for (int v = 0; v < VT; v++) s += As[tid * 32 + v];
        }
        rowsA[tid] = s;
    }

    // stage B: B[row][u] = sum_v A[u,v] * X[row][v]   (A via broadcast float4 LDS)
    {
        float4 xr[8];
        const float4* Xr4 = (const float4*)(Xs + tid * 36);
#pragma unroll
        for (int i = 0; i < 8; i++) xr[i] = Xr4[i];
        const float4* A4 = (const float4*)As;
        float* brow = Bs + tid * 28;
#pragma unroll 5
        for (int u = 0; u < 25; u++) {
            float acc = 0.f;
#pragma unroll
            for (int i = 0; i < 8; i++) {
                float4 a = A4[u * 8 + i];
                acc += a.x * xr[i].x + a.y * xr[i].y + a.z * xr[i].z + a.w * xr[i].w;
            }
            brow[u] = acc;
        }
    }
    __syncthreads();

    // stage C: Y[o][tt][u] = b[o]*rowsA[u] + sum_c W[o,c]*B[c*8+tt][u], then epilogue
    {
        int o = tid >> 3;
        int ttl = tid & 7;
        int oo = k * OG + o;
        float bterm = cdb[k * OG + o];
        float acc[28];
#pragma unroll
        for (int u = 0; u < 28; u++) acc[u] = bterm * rowsA[u];
        const float4* B4 = (const float4*)Bs;
#pragma unroll 4
        for (int c = 0; c < 32; c++) {
            float w = Ws[o * 33 + c];
            const float4* brow = B4 + (c * 8 + ttl) * 7;
#pragma unroll
            for (int i = 0; i < 7; i++) {
                float4 b = brow[i];
                acc[4 * i + 0] += w * b.x;
                acc[4 * i + 1] += w * b.y;
                acc[4 * i + 2] += w * b.z;
                acc[4 * i + 3] += w * b.w;
            }
        }
        float scale = gam[oo] / sqrtf(1.0f + 1e-5f);
        float bb = bet[oo];
        int t = tb * 8 + ttl;
        int base = ((n * Cc + oo) * Tt + t) * Vv;
#pragma unroll
        for (int u = 0; u < 25; u++) {
            float val = acc[u] * scale + bb + x[base + u];
            out[base + u] = fmaxf(val, 0.f);
        }
    }
}

// ---------------- kernel 4: copy hyper_joint into output tail ----------------
__global__ void k_tail(const float* __restrict__ hj, float* __restrict__ out, int tail) {
    int i = blockIdx.x * blockDim.x + threadIdx.x;
    if (i < tail && i < VNh * Cc) out[(size_t)Nn * OO * Tt * Vv + i] = hj[i];
}

// ---------------- launch ----------------
extern "C" void kernel_launch(void* const* d_in, const int* in_sizes, int n_in,
                              void* d_out, int out_size) {
    const float* x    = (const float*)d_in[0];
    const float* adjc = (const float*)d_in[1];
    const float* ei   = (const float*)d_in[2];
    const float* hj   = (const float*)d_in[3];
    const float* alp  = (const float*)d_in[4];
    const float* tvw  = (const float*)d_in[5];
    const float* tvb  = (const float*)d_in[6];
    const float* t1w  = (const float*)d_in[7];
    const float* t1b  = (const float*)d_in[8];
    const float* t2w  = (const float*)d_in[9];
    const float* t2b  = (const float*)d_in[10];
    const float* cdw  = (const float*)d_in[11];
    const float* cdb  = (const float*)d_in[12];
    const float* gam  = (const float*)d_in[13];
    const float* bet  = (const float*)d_in[14];
    float* out = (float*)d_out;

    k_adjn<<<1, 256>>>(adjc, ei);
    k_pool<<<(Nn * Cc * VT + 255) / 256, 256>>>(x, hj);
    k_hyper<<<Nn, 256>>>(tvw, tvb, t1w, t1b, t2w, t2b, alp);

    cudaFuncSetAttribute(k_main, cudaFuncAttributeMaxDynamicSharedMemorySize,
                         SM_TOTAL_FLOATS * 4);
    k_main<<<Nn * Kk * (Tt / 8), 256, SM_TOTAL_FLOATS * 4>>>(x, hj, cdw, cdb, gam, bet, out);

    int tail = out_size - Nn * OO * Tt * Vv;
    if (tail > 0) {
        k_tail<<<(tail + 255) / 256, 256>>>(hj, out, tail);
    }
}